// round 5
// baseline (speedup 1.0000x reference)
#include <cuda_runtime.h>

#define BATCH 8
#define HH 2048
#define WW 2048
#define PATCH 16
#define DD 16
#define FEAT 256
#define NPIX (128 * 128)

typedef unsigned long long ull;
typedef unsigned int uint;

// ---------------- device scratch ----------------
__device__ float g_tc[256];
__device__ float g_ts[256];
__device__ float g_R[DD][FEAT];
__device__ float g_I[DD][FEAT];
__device__ __align__(16) float2 g_M[FEAT][DD / 2];   // M[f][k] pairs along k
__device__ float g_c[DD];
__device__ float g_img[BATCH * DD * NPIX];           // 8 MB [b][d][i][j]
__device__ float g_ps[1024];                         // partials [bd*8+slice]
__device__ float g_pq[1024];

// ---------------- packed f32x2 helpers ----------------
__device__ __forceinline__ ull packf2(float lo, float hi) {
    ull r; asm("mov.b64 %0, {%1, %2};" : "=l"(r) : "f"(lo), "f"(hi)); return r;
}
__device__ __forceinline__ void fmaf2(ull& d, ull a, ull b) {
    asm("fma.rn.f32x2 %0, %1, %2, %0;" : "+l"(d) : "l"(a), "l"(b));
}
__device__ __forceinline__ ull addf2(ull a, ull b) {
    ull r; asm("add.rn.f32x2 %0, %1, %2;" : "=l"(r) : "l"(a), "l"(b)); return r;
}
__device__ __forceinline__ void unpackf2(ull v, float& lo, float& hi) {
    asm("mov.b64 {%0, %1}, %2;" : "=f"(lo), "=f"(hi) : "l"(v));
}
__device__ __forceinline__ void lds_v2u64(ull& a, ull& b, uint addr) {
    asm volatile("ld.shared.v2.u64 {%0, %1}, [%2];" : "=l"(a), "=l"(b) : "r"(addr));
}
__device__ __forceinline__ void cpasync16(uint saddr, const void* gaddr) {
    asm volatile("cp.async.cg.shared.global [%0], [%1], 16;" :: "r"(saddr), "l"(gaddr));
}
__device__ __forceinline__ void cp_commit() {
    asm volatile("cp.async.commit_group;");
}
__device__ __forceinline__ void cp_wait2() {
    asm volatile("cp.async.wait_group 2;");
}

// ---------------- K1: table + R[j,f], I[j,f] ----------------
__global__ void k_prep1(const float* __restrict__ Wr, const float* __restrict__ Wi) {
    __shared__ float sc[256], ss[256], wr[256], wi[256];
    int f = threadIdx.x, j = blockIdx.x;
    float s, c;
    sincospif((float)f * (1.0f / 128.0f), &s, &c);
    sc[f] = c; ss[f] = s;
    if (j == 0) { g_tc[f] = c; g_ts[f] = s; }
    wr[f] = Wr[j * FEAT + f]; wi[f] = Wi[j * FEAT + f];
    __syncthreads();
    float R = 0.f, I = 0.f;
    for (int d = 0; d < 256; ++d) {
        int t = (d * f) & 255;
        float cc = sc[t], s2 = ss[t];
        R += wr[d] * cc + wi[d] * s2;
        I += wi[d] * cc - wr[d] * s2;
    }
    g_R[j][f] = R; g_I[j][f] = I;
}

// ---------------- K2: M[f,k], c[k] ----------------
__global__ void k_prep2(const float* __restrict__ br, const float* __restrict__ bi) {
    int e = blockIdx.x * 256 + threadIdx.x;
    int f = e >> 4, k = e & 15;
    float m = 0.f;
    for (int j = 0; j < DD; ++j) {
        int t = (16 * j * k) & 255;
        m += g_R[j][f] * g_tc[t] - g_I[j][f] * g_ts[t];
    }
    ((float*)g_M)[f * DD + k] = m * (1.0f / 16.0f);
    if (e < DD) {
        float cc = 0.f;
        for (int j = 0; j < DD; ++j) {
            int t = (16 * j * e) & 255;
            cc += (br[j] - bi[j]) * g_tc[t] - (br[j] + bi[j]) * g_ts[t];
        }
        g_c[e] = cc * (1.0f / 16.0f);
    }
}

// ---------------- K3: main patch GEMM with cp.async pipeline ----------------
// Block = (b, ph, seg64): 64 patches x 16 rows. 4-stage x 4KB smem ring.
// Warp w: patches w*16..w*16+15 (2 streams of 8), ALL 16 k (acc[2][8]).
// lane l: a=l>>2 (patch in stream), q=l&3 (s2 quad).
__global__ void __launch_bounds__(128, 6) k_main(const float* __restrict__ x) {
    __shared__ uint4 sM[FEAT * 4];        // swizzled: row f, unit m at col (m+(f>>2))&3
    __shared__ float scc[DD];
    __shared__ float sX[4][1024];         // 4 stages x 4KB
    int tid = threadIdx.x;
    {
        const uint4* gm = (const uint4*)g_M;
        for (int f = tid; f < 256; f += 128)
#pragma unroll
            for (int m = 0; m < 4; ++m)
                sM[f * 4 + ((m + (f >> 2)) & 3)] = gm[f * 4 + m];
        if (tid < DD) scc[tid] = g_c[tid];
    }

    int blk = blockIdx.x;                 // 2048 blocks
    int b = blk >> 8;
    int r = blk & 255;
    int ph = r >> 1;
    int seg = r & 1;
    const float* gbase = x + (size_t)b * HH * WW + (size_t)(ph * PATCH) * WW + seg * 1024;

    uint sXaddr = (uint)__cvta_generic_to_shared(sX);
    // prologue: rows 0..2 into stages 0..2
#pragma unroll
    for (int st = 0; st < 3; ++st) {
        const float* src = gbase + (size_t)st * WW;
        uint dst = sXaddr + (uint)st * 4096 + (uint)tid * 16;
        cpasync16(dst, src + tid * 4);
        cpasync16(dst + 2048, src + 512 + tid * 4);
        cp_commit();
    }

    uint sMaddr = (uint)__cvta_generic_to_shared(sM);
    int lane = tid & 31;
    int w = tid >> 5;
    int a = lane >> 2;
    int q = lane & 3;

    ull acc[2][8];
    ull z = packf2(0.f, 0.f);
#pragma unroll
    for (int t = 0; t < 2; ++t)
#pragma unroll
        for (int p = 0; p < 8; ++p) acc[t][p] = z;

    uint xoff = (uint)(w * 256) + (uint)(lane * 4);   // floats

#pragma unroll 1
    for (int s1 = 0; s1 < PATCH; ++s1) {
        cp_wait2();
        __syncthreads();
        const float* xs = sX[s1 & 3];
        float4 cur0 = *(const float4*)(xs + xoff);
        float4 cur1 = *(const float4*)(xs + xoff + 128);
        uint rowbase = sMaddr + (uint)(s1 * 16 + q * 4) * 64;
#pragma unroll
        for (int e = 0; e < 4; ++e) {
            uint ra = rowbase + (uint)e * 64;
            ull mk[8];
#pragma unroll
            for (int m = 0; m < 4; ++m)
                lds_v2u64(mk[2 * m], mk[2 * m + 1], ra + (uint)(((m + q) & 3) << 4));
            float x0 = (e == 0) ? cur0.x : (e == 1) ? cur0.y : (e == 2) ? cur0.z : cur0.w;
            float x1 = (e == 0) ? cur1.x : (e == 1) ? cur1.y : (e == 2) ? cur1.z : cur1.w;
            ull v0 = packf2(x0, x0);
            ull v1 = packf2(x1, x1);
#pragma unroll
            for (int p = 0; p < 8; ++p) {
                fmaf2(acc[0][p], v0, mk[p]);
                fmaf2(acc[1][p], v1, mk[p]);
            }
        }
        if (s1 < 13) {
            const float* src = gbase + (size_t)(s1 + 3) * WW;
            uint dst = sXaddr + (uint)((s1 + 3) & 3) * 4096 + (uint)tid * 16;
            cpasync16(dst, src + tid * 4);
            cpasync16(dst + 2048, src + 512 + tid * 4);
        }
        cp_commit();
    }

    // reduce-scatter acc[t][0..7] over the 4 quad lanes -> 2 k-pairs per lane
    int kb = ((q & 1) << 2) | (q & 2);
    float* gp = g_img + (size_t)b * DD * NPIX + ph * 128 + seg * 64 + w * 16;
#pragma unroll
    for (int t = 0; t < 2; ++t) {
        ull tmp[4], fin[2];
#pragma unroll
        for (int jj = 0; jj < 4; ++jj) {
            ull send = (q & 1) ? acc[t][jj] : acc[t][jj + 4];
            ull keep = (q & 1) ? acc[t][jj + 4] : acc[t][jj];
            tmp[jj] = addf2(keep, __shfl_xor_sync(0xffffffffu, send, 1));
        }
#pragma unroll
        for (int jj = 0; jj < 2; ++jj) {
            ull send = (q & 2) ? tmp[jj] : tmp[jj + 2];
            ull keep = (q & 2) ? tmp[jj + 2] : tmp[jj];
            fin[jj] = addf2(keep, __shfl_xor_sync(0xffffffffu, send, 2));
        }
        int col = t * 8 + a;
#pragma unroll
        for (int jj = 0; jj < 2; ++jj) {
            int k0 = 2 * (kb + jj);
            ull v = addf2(fin[jj], packf2(scc[k0], scc[k0 + 1]));
            float lo, hi;
            unpackf2(v, lo, hi);
            gp[(size_t)k0 * NPIX + col] = lo;
            gp[(size_t)(k0 + 1) * NPIX + col] = hi;
        }
    }
}

// ---------------- float4 + shfl rolling 3x3 conv ----------------
__device__ __forceinline__ void conv_rows(float4 v, int lane, const float* w,
                                          float4& h0, float4& h1, float4& h2) {
    float l = __shfl_up_sync(0xffffffffu, v.w, 1);
    float rr = __shfl_down_sync(0xffffffffu, v.x, 1);
    if (lane == 0) l = 0.f;
    if (lane == 31) rr = 0.f;
    float lx = l, ly = v.x, lz = v.y, lw = v.z;
    float rx = v.y, ry = v.z, rz = v.w, rw = rr;
#define HROW(H, W0, W1, W2)                                   \
    H.x = W0 * lx + W1 * v.x + W2 * rx;                       \
    H.y = W0 * ly + W1 * v.y + W2 * ry;                       \
    H.z = W0 * lz + W1 * v.z + W2 * rz;                       \
    H.w = W0 * lw + W1 * v.w + W2 * rw;
    HROW(h0, w[0], w[1], w[2])
    HROW(h1, w[3], w[4], w[5])
    HROW(h2, w[6], w[7], w[8])
#undef HROW
}

__device__ __forceinline__ float4 ld_row(const float* __restrict__ base, int r, int lane) {
    if ((unsigned)r < 128u) return ((const float4*)(base + r * 128))[lane];
    return make_float4(0.f, 0.f, 0.f, 0.f);
}

// ---------------- K4: conv + partial stats (warp = 4 output rows) -------------
__global__ void __launch_bounds__(128) k_stats(const float* __restrict__ cw,
                                               const float* __restrict__ cb) {
    int blk = blockIdx.x;            // bd*8 + slice
    int bd = blk >> 3;
    int d = bd & 15;
    int slice = blk & 7;
    int tid = threadIdx.x;
    int lane = tid & 31, wp = tid >> 5;
    int r0 = slice * 16 + wp * 4;
    float w[9];
#pragma unroll
    for (int t = 0; t < 9; ++t) w[t] = cw[d * 9 + t];
    float bias = cb[d];
    const float* base = g_img + (size_t)bd * NPIX;

    float4 A = make_float4(0, 0, 0, 0), B = make_float4(0, 0, 0, 0);
    float s = 0.f, sq = 0.f;
#pragma unroll
    for (int r = r0 - 1; r <= r0 + 4; ++r) {
        float4 v = ld_row(base, r, lane);
        float4 h0, h1, h2;
        conv_rows(v, lane, w, h0, h1, h2);
        if (r >= r0 + 1) {
            float vx = A.x + h2.x + bias, vy = A.y + h2.y + bias;
            float vz = A.z + h2.z + bias, vw = A.w + h2.w + bias;
            s += vx + vy + vz + vw;
            sq += vx * vx + vy * vy + vz * vz + vw * vw;
        }
        A.x = B.x + h1.x; A.y = B.y + h1.y; A.z = B.z + h1.z; A.w = B.w + h1.w;
        B = h0;
    }
#pragma unroll
    for (int off = 16; off; off >>= 1) {
        s += __shfl_down_sync(0xffffffffu, s, off);
        sq += __shfl_down_sync(0xffffffffu, sq, off);
    }
    __shared__ float rs[4], rq[4];
    if (lane == 0) { rs[wp] = s; rq[wp] = sq; }
    __syncthreads();
    if (tid == 0) {
        g_ps[blk] = rs[0] + rs[1] + rs[2] + rs[3];
        g_pq[blk] = rq[0] + rq[1] + rq[2] + rq[3];
    }
}

// ---------------- K5: BN finalize (in-block) + conv + BN + write --------------
__global__ void __launch_bounds__(128) k_out(const float* __restrict__ cw,
                                             const float* __restrict__ cb,
                                             const float* __restrict__ gamma,
                                             const float* __restrict__ beta,
                                             float* __restrict__ out) {
    int blk = blockIdx.x;
    int bd = blk >> 3;
    int d = bd & 15;
    int slice = blk & 7;
    int tid = threadIdx.x;
    int lane = tid & 31, wp = tid >> 5;
    int r0 = slice * 16 + wp * 4;

    __shared__ float sp[64], sq2[64];
    __shared__ float smu, ssc;
    if (tid < 64) {
        int bb = tid >> 3, sl = tid & 7;
        int idx = ((bb * DD + d) << 3) + sl;
        sp[tid] = g_ps[idx];
        sq2[tid] = g_pq[idx];
    }
    __syncthreads();
    for (int off = 32; off; off >>= 1) {
        if (tid < off) { sp[tid] += sp[tid + off]; sq2[tid] += sq2[tid + off]; }
        __syncthreads();
    }
    if (tid == 0) {
        float n = 131072.0f;
        float mu = sp[0] / n;
        float var = sq2[0] / n - mu * mu;
        smu = mu;
        ssc = rsqrtf(var + 1e-5f) * gamma[d];
    }
    float w[9];
#pragma unroll
    for (int t = 0; t < 9; ++t) w[t] = cw[d * 9 + t];
    float bias = cb[d];
    const float* base = g_img + (size_t)bd * NPIX;
    __syncthreads();
    float mu = smu, sc = ssc, bt = beta[d];

    float4 A = make_float4(0, 0, 0, 0), B = make_float4(0, 0, 0, 0);
    float4* op = (float4*)(out + (size_t)bd * NPIX) + lane;
#pragma unroll
    for (int r = r0 - 1; r <= r0 + 4; ++r) {
        float4 v = ld_row(base, r, lane);
        float4 h0, h1, h2;
        conv_rows(v, lane, w, h0, h1, h2);
        if (r >= r0 + 1) {
            float4 o;
            o.x = (A.x + h2.x + bias - mu) * sc + bt;
            o.y = (A.y + h2.y + bias - mu) * sc + bt;
            o.z = (A.z + h2.z + bias - mu) * sc + bt;
            o.w = (A.w + h2.w + bias - mu) * sc + bt;
            op[(r - 1) * 32] = o;
        }
        A.x = B.x + h1.x; A.y = B.y + h1.y; A.z = B.z + h1.z; A.w = B.w + h1.w;
        B = h0;
    }
}

extern "C" void kernel_launch(void* const* d_in, const int* in_sizes, int n_in,
                              void* d_out, int out_size) {
    const float* x = (const float*)d_in[0];
    const float* Wr = (const float*)d_in[1];
    const float* br = (const float*)d_in[2];
    const float* Wi = (const float*)d_in[3];
    const float* bi = (const float*)d_in[4];
    const float* cw = (const float*)d_in[5];
    const float* cb = (const float*)d_in[6];
    const float* gamma = (const float*)d_in[7];
    const float* beta = (const float*)d_in[8];
    float* out = (float*)d_out;

    k_prep1<<<16, 256>>>(Wr, Wi);
    k_prep2<<<16, 256>>>(br, bi);
    k_main<<<2048, 128>>>(x);
    k_stats<<<1024, 128>>>(cw, cb);
    k_out<<<1024, 128>>>(cw, cb, gamma, beta, out);
}

// round 6
// speedup vs baseline: 1.1760x; 1.1760x over previous
#include <cuda_runtime.h>

#define BATCH 8
#define HH 2048
#define WW 2048
#define PATCH 16
#define DD 16
#define FEAT 256
#define NPIX (128 * 128)

typedef unsigned long long ull;
typedef unsigned int uint;

// ---------------- device scratch ----------------
__device__ float g_tc[256];
__device__ float g_ts[256];
__device__ float g_R[DD][FEAT];
__device__ float g_I[DD][FEAT];
__device__ __align__(16) float2 g_M[FEAT][DD / 2];   // M[f][k] pairs along k
__device__ float g_c[DD];
__device__ float g_img[BATCH * DD * NPIX];           // 8 MB [b][d][i][j]
__device__ float g_ps[1024];                         // partials [bd*8+slice]
__device__ float g_pq[1024];

// ---------------- packed f32x2 helpers ----------------
__device__ __forceinline__ ull packf2(float lo, float hi) {
    ull r; asm("mov.b64 %0, {%1, %2};" : "=l"(r) : "f"(lo), "f"(hi)); return r;
}
__device__ __forceinline__ void fmaf2(ull& d, ull a, ull b) {
    asm("fma.rn.f32x2 %0, %1, %2, %0;" : "+l"(d) : "l"(a), "l"(b));
}
__device__ __forceinline__ ull addf2(ull a, ull b) {
    ull r; asm("add.rn.f32x2 %0, %1, %2;" : "=l"(r) : "l"(a), "l"(b)); return r;
}
__device__ __forceinline__ void unpackf2(ull v, float& lo, float& hi) {
    asm("mov.b64 {%0, %1}, %2;" : "=f"(lo), "=f"(hi) : "l"(v));
}
__device__ __forceinline__ void lds_v2u64(ull& a, ull& b, uint addr) {
    asm volatile("ld.shared.v2.u64 {%0, %1}, [%2];" : "=l"(a), "=l"(b) : "r"(addr));
}
__device__ __forceinline__ void pref_l2(const void* p) {
    asm volatile("prefetch.global.L2 [%0];" :: "l"(p));
}

// ---------------- K1: table + R[j,f], I[j,f] ----------------
__global__ void k_prep1(const float* __restrict__ Wr, const float* __restrict__ Wi) {
    __shared__ float sc[256], ss[256], wr[256], wi[256];
    int f = threadIdx.x, j = blockIdx.x;
    float s, c;
    sincospif((float)f * (1.0f / 128.0f), &s, &c);
    sc[f] = c; ss[f] = s;
    if (j == 0) { g_tc[f] = c; g_ts[f] = s; }
    wr[f] = Wr[j * FEAT + f]; wi[f] = Wi[j * FEAT + f];
    __syncthreads();
    float R = 0.f, I = 0.f;
    for (int d = 0; d < 256; ++d) {
        int t = (d * f) & 255;
        float cc = sc[t], s2 = ss[t];
        R += wr[d] * cc + wi[d] * s2;
        I += wi[d] * cc - wr[d] * s2;
    }
    g_R[j][f] = R; g_I[j][f] = I;
}

// ---------------- K2: M[f,k], c[k] ----------------
__global__ void k_prep2(const float* __restrict__ br, const float* __restrict__ bi) {
    int e = blockIdx.x * 256 + threadIdx.x;
    int f = e >> 4, k = e & 15;
    float m = 0.f;
    for (int j = 0; j < DD; ++j) {
        int t = (16 * j * k) & 255;
        m += g_R[j][f] * g_tc[t] - g_I[j][f] * g_ts[t];
    }
    ((float*)g_M)[f * DD + k] = m * (1.0f / 16.0f);
    if (e < DD) {
        float cc = 0.f;
        for (int j = 0; j < DD; ++j) {
            int t = (16 * j * e) & 255;
            cc += (br[j] - bi[j]) * g_tc[t] - (br[j] + bi[j]) * g_ts[t];
        }
        g_c[e] = cc * (1.0f / 16.0f);
    }
}

// ---------------- K3: main patch GEMM ----------------
// Warp = 16 adjacent patches (2 streams of 8), ALL 16 k (acc[2][8] = 32 regs).
// lane l: a=l>>2 (patch sub-index), q=l&3 (s2 quad).
// Per s1: 2 coalesced LDG.128 (1KB/warp, L2-prefetched 4 rows ahead),
// 8 broadcast LDS.128 of M feed 64 FMA2. 50% occupancy target.
__global__ void __launch_bounds__(256, 4) k_main(const float* __restrict__ x) {
    __shared__ uint4 sM[FEAT * 4];   // row f: unit m stored at col (m+(f>>2))&3
    __shared__ float scc[DD];
    int tid = threadIdx.x;

    int lane = tid & 31;
    int warp = tid >> 5;
    int u = blockIdx.x * 8 + warp;          // 8192 warp units
    int b = u >> 10;
    int r = u & 1023;
    int ph = r >> 3;                        // patch row
    int seg = r & 7;                        // 16-patch column segment
    int a = lane >> 2;
    int q = lane & 3;

    const float* gbase = x + (size_t)b * HH * WW + (size_t)(ph * PATCH) * WW + seg * 256;

    // prefetch first rows into L2 while staging M
#pragma unroll
    for (int rr = 0; rr < 4; ++rr)
        pref_l2(gbase + (size_t)rr * WW + (lane & 7) * 32);

    {
        const uint4* gm = (const uint4*)g_M;
        int f = tid;
#pragma unroll
        for (int m = 0; m < 4; ++m)
            sM[f * 4 + ((m + (f >> 2)) & 3)] = gm[f * 4 + m];
        if (tid < DD) scc[tid] = g_c[tid];
    }
    __syncthreads();

    uint sMaddr = (uint)__cvta_generic_to_shared(sM);

    ull acc[2][8];
    ull z = packf2(0.f, 0.f);
#pragma unroll
    for (int t = 0; t < 2; ++t)
#pragma unroll
        for (int p = 0; p < 8; ++p) acc[t][p] = z;

#pragma unroll 1
    for (int s1 = 0; s1 < PATCH; ++s1) {
        if (s1 < 12) pref_l2(gbase + (size_t)(s1 + 4) * WW + (lane & 7) * 32);
        const float4* rp = (const float4*)(gbase + (size_t)s1 * WW);
        float4 cur0 = rp[lane];
        float4 cur1 = rp[32 + lane];
        uint rowbase = sMaddr + (uint)(s1 * 16 + q * 4) * 64;
#pragma unroll
        for (int e = 0; e < 4; ++e) {
            uint ra = rowbase + (uint)e * 64;
            ull mk[8];
#pragma unroll
            for (int m = 0; m < 4; ++m)
                lds_v2u64(mk[2 * m], mk[2 * m + 1], ra + (uint)(((m + q) & 3) << 4));
            float x0 = (e == 0) ? cur0.x : (e == 1) ? cur0.y : (e == 2) ? cur0.z : cur0.w;
            float x1 = (e == 0) ? cur1.x : (e == 1) ? cur1.y : (e == 2) ? cur1.z : cur1.w;
            ull v0 = packf2(x0, x0);
            ull v1 = packf2(x1, x1);
#pragma unroll
            for (int p = 0; p < 8; ++p) {
                fmaf2(acc[0][p], v0, mk[p]);
                fmaf2(acc[1][p], v1, mk[p]);
            }
        }
    }

    // reduce-scatter acc[t][0..7] over the 4 quad lanes -> 2 k-pairs per lane
    int kb = ((q & 1) << 2) | (q & 2);
    float* gp = g_img + (size_t)b * DD * NPIX + ph * 128 + seg * 16;
#pragma unroll
    for (int t = 0; t < 2; ++t) {
        ull tmp[4], fin[2];
#pragma unroll
        for (int jj = 0; jj < 4; ++jj) {
            ull send = (q & 1) ? acc[t][jj] : acc[t][jj + 4];
            ull keep = (q & 1) ? acc[t][jj + 4] : acc[t][jj];
            tmp[jj] = addf2(keep, __shfl_xor_sync(0xffffffffu, send, 1));
        }
#pragma unroll
        for (int jj = 0; jj < 2; ++jj) {
            ull send = (q & 2) ? tmp[jj] : tmp[jj + 2];
            ull keep = (q & 2) ? tmp[jj + 2] : tmp[jj];
            fin[jj] = addf2(keep, __shfl_xor_sync(0xffffffffu, send, 2));
        }
        int col = t * 8 + a;
#pragma unroll
        for (int jj = 0; jj < 2; ++jj) {
            int k0 = 2 * (kb + jj);
            ull v = addf2(fin[jj], packf2(scc[k0], scc[k0 + 1]));
            float lo, hi;
            unpackf2(v, lo, hi);
            gp[(size_t)k0 * NPIX + col] = lo;
            gp[(size_t)(k0 + 1) * NPIX + col] = hi;
        }
    }
}

// ---------------- float4 + shfl rolling 3x3 conv ----------------
__device__ __forceinline__ void conv_rows(float4 v, int lane, const float* w,
                                          float4& h0, float4& h1, float4& h2) {
    float l = __shfl_up_sync(0xffffffffu, v.w, 1);
    float rr = __shfl_down_sync(0xffffffffu, v.x, 1);
    if (lane == 0) l = 0.f;
    if (lane == 31) rr = 0.f;
    float lx = l, ly = v.x, lz = v.y, lw = v.z;
    float rx = v.y, ry = v.z, rz = v.w, rw = rr;
#define HROW(H, W0, W1, W2)                                   \
    H.x = W0 * lx + W1 * v.x + W2 * rx;                       \
    H.y = W0 * ly + W1 * v.y + W2 * ry;                       \
    H.z = W0 * lz + W1 * v.z + W2 * rz;                       \
    H.w = W0 * lw + W1 * v.w + W2 * rw;
    HROW(h0, w[0], w[1], w[2])
    HROW(h1, w[3], w[4], w[5])
    HROW(h2, w[6], w[7], w[8])
#undef HROW
}

__device__ __forceinline__ float4 ld_row(const float* __restrict__ base, int r, int lane) {
    if ((unsigned)r < 128u) return ((const float4*)(base + r * 128))[lane];
    return make_float4(0.f, 0.f, 0.f, 0.f);
}

// ---------------- K4: conv + partial stats (warp = 4 output rows) -------------
__global__ void __launch_bounds__(128) k_stats(const float* __restrict__ cw,
                                               const float* __restrict__ cb) {
    int blk = blockIdx.x;            // bd*8 + slice
    int bd = blk >> 3;
    int d = bd & 15;
    int slice = blk & 7;
    int tid = threadIdx.x;
    int lane = tid & 31, wp = tid >> 5;
    int r0 = slice * 16 + wp * 4;
    float w[9];
#pragma unroll
    for (int t = 0; t < 9; ++t) w[t] = cw[d * 9 + t];
    float bias = cb[d];
    const float* base = g_img + (size_t)bd * NPIX;

    float4 A = make_float4(0, 0, 0, 0), B = make_float4(0, 0, 0, 0);
    float s = 0.f, sq = 0.f;
#pragma unroll
    for (int r = r0 - 1; r <= r0 + 4; ++r) {
        float4 v = ld_row(base, r, lane);
        float4 h0, h1, h2;
        conv_rows(v, lane, w, h0, h1, h2);
        if (r >= r0 + 1) {
            float vx = A.x + h2.x + bias, vy = A.y + h2.y + bias;
            float vz = A.z + h2.z + bias, vw = A.w + h2.w + bias;
            s += vx + vy + vz + vw;
            sq += vx * vx + vy * vy + vz * vz + vw * vw;
        }
        A.x = B.x + h1.x; A.y = B.y + h1.y; A.z = B.z + h1.z; A.w = B.w + h1.w;
        B = h0;
    }
#pragma unroll
    for (int off = 16; off; off >>= 1) {
        s += __shfl_down_sync(0xffffffffu, s, off);
        sq += __shfl_down_sync(0xffffffffu, sq, off);
    }
    __shared__ float rs[4], rq[4];
    if (lane == 0) { rs[wp] = s; rq[wp] = sq; }
    __syncthreads();
    if (tid == 0) {
        g_ps[blk] = rs[0] + rs[1] + rs[2] + rs[3];
        g_pq[blk] = rq[0] + rq[1] + rq[2] + rq[3];
    }
}

// ---------------- K5: BN finalize (in-block) + conv + BN + write --------------
__global__ void __launch_bounds__(128) k_out(const float* __restrict__ cw,
                                             const float* __restrict__ cb,
                                             const float* __restrict__ gamma,
                                             const float* __restrict__ beta,
                                             float* __restrict__ out) {
    int blk = blockIdx.x;
    int bd = blk >> 3;
    int d = bd & 15;
    int slice = blk & 7;
    int tid = threadIdx.x;
    int lane = tid & 31, wp = tid >> 5;
    int r0 = slice * 16 + wp * 4;

    __shared__ float sp[64], sq2[64];
    __shared__ float smu, ssc;
    if (tid < 64) {
        int bb = tid >> 3, sl = tid & 7;
        int idx = ((bb * DD + d) << 3) + sl;
        sp[tid] = g_ps[idx];
        sq2[tid] = g_pq[idx];
    }
    __syncthreads();
    for (int off = 32; off; off >>= 1) {
        if (tid < off) { sp[tid] += sp[tid + off]; sq2[tid] += sq2[tid + off]; }
        __syncthreads();
    }
    if (tid == 0) {
        float n = 131072.0f;
        float mu = sp[0] / n;
        float var = sq2[0] / n - mu * mu;
        smu = mu;
        ssc = rsqrtf(var + 1e-5f) * gamma[d];
    }
    float w[9];
#pragma unroll
    for (int t = 0; t < 9; ++t) w[t] = cw[d * 9 + t];
    float bias = cb[d];
    const float* base = g_img + (size_t)bd * NPIX;
    __syncthreads();
    float mu = smu, sc = ssc, bt = beta[d];

    float4 A = make_float4(0, 0, 0, 0), B = make_float4(0, 0, 0, 0);
    float4* op = (float4*)(out + (size_t)bd * NPIX) + lane;
#pragma unroll
    for (int r = r0 - 1; r <= r0 + 4; ++r) {
        float4 v = ld_row(base, r, lane);
        float4 h0, h1, h2;
        conv_rows(v, lane, w, h0, h1, h2);
        if (r >= r0 + 1) {
            float4 o;
            o.x = (A.x + h2.x + bias - mu) * sc + bt;
            o.y = (A.y + h2.y + bias - mu) * sc + bt;
            o.z = (A.z + h2.z + bias - mu) * sc + bt;
            o.w = (A.w + h2.w + bias - mu) * sc + bt;
            op[(r - 1) * 32] = o;
        }
        A.x = B.x + h1.x; A.y = B.y + h1.y; A.z = B.z + h1.z; A.w = B.w + h1.w;
        B = h0;
    }
}

extern "C" void kernel_launch(void* const* d_in, const int* in_sizes, int n_in,
                              void* d_out, int out_size) {
    const float* x = (const float*)d_in[0];
    const float* Wr = (const float*)d_in[1];
    const float* br = (const float*)d_in[2];
    const float* Wi = (const float*)d_in[3];
    const float* bi = (const float*)d_in[4];
    const float* cw = (const float*)d_in[5];
    const float* cb = (const float*)d_in[6];
    const float* gamma = (const float*)d_in[7];
    const float* beta = (const float*)d_in[8];
    float* out = (float*)d_out;

    k_prep1<<<16, 256>>>(Wr, Wi);
    k_prep2<<<16, 256>>>(br, bi);
    k_main<<<1024, 256>>>(x);
    k_stats<<<1024, 128>>>(cw, cb);
    k_out<<<1024, 128>>>(cw, cb, gamma, beta, out);
}

// round 7
// speedup vs baseline: 1.3266x; 1.1280x over previous
#include <cuda_runtime.h>

#define BATCH 8
#define HH 2048
#define WW 2048
#define PATCH 16
#define DD 16
#define FEAT 256
#define NPIX (128 * 128)

typedef unsigned long long ull;
typedef unsigned int uint;

// ---------------- device scratch ----------------
__device__ float g_tc[256];
__device__ float g_ts[256];
__device__ float g_R[DD][FEAT];
__device__ float g_I[DD][FEAT];
__device__ __align__(16) float2 g_M[FEAT][DD / 2];   // M[f][k] pairs along k
__device__ float g_c[DD];
__device__ float g_img[BATCH * DD * NPIX];           // 8 MB [b][d][i][j]
__device__ float g_ps[1024];                         // partials [bd*8+slice]
__device__ float g_pq[1024];
__device__ int g_cnt[DD];                            // per-channel arrival counters

// ---------------- packed f32x2 helpers ----------------
__device__ __forceinline__ ull packf2(float lo, float hi) {
    ull r; asm("mov.b64 %0, {%1, %2};" : "=l"(r) : "f"(lo), "f"(hi)); return r;
}
__device__ __forceinline__ void fmaf2(ull& d, ull a, ull b) {
    asm("fma.rn.f32x2 %0, %1, %2, %0;" : "+l"(d) : "l"(a), "l"(b));
}
__device__ __forceinline__ ull addf2(ull a, ull b) {
    ull r; asm("add.rn.f32x2 %0, %1, %2;" : "=l"(r) : "l"(a), "l"(b)); return r;
}
__device__ __forceinline__ void unpackf2(ull v, float& lo, float& hi) {
    asm("mov.b64 {%0, %1}, %2;" : "=f"(lo), "=f"(hi) : "l"(v));
}
__device__ __forceinline__ void lds_v2u64(ull& a, ull& b, uint addr) {
    asm volatile("ld.shared.v2.u64 {%0, %1}, [%2];" : "=l"(a), "=l"(b) : "r"(addr));
}

// ---------------- K1: table + R[j,f], I[j,f] ----------------
__global__ void k_prep1(const float* __restrict__ Wr, const float* __restrict__ Wi) {
    __shared__ float sc[256], ss[256], wr[256], wi[256];
    int f = threadIdx.x, j = blockIdx.x;
    float s, c;
    sincospif((float)f * (1.0f / 128.0f), &s, &c);
    sc[f] = c; ss[f] = s;
    if (j == 0) { g_tc[f] = c; g_ts[f] = s; }
    wr[f] = Wr[j * FEAT + f]; wi[f] = Wi[j * FEAT + f];
    __syncthreads();
    float R = 0.f, I = 0.f;
    for (int d = 0; d < 256; ++d) {
        int t = (d * f) & 255;
        float cc = sc[t], s2 = ss[t];
        R += wr[d] * cc + wi[d] * s2;
        I += wi[d] * cc - wr[d] * s2;
    }
    g_R[j][f] = R; g_I[j][f] = I;
}

// ---------------- K2: M[f,k], c[k]; also reset counters ----------------
__global__ void k_prep2(const float* __restrict__ br, const float* __restrict__ bi) {
    int e = blockIdx.x * 256 + threadIdx.x;
    int f = e >> 4, k = e & 15;
    float m = 0.f;
    for (int j = 0; j < DD; ++j) {
        int t = (16 * j * k) & 255;
        m += g_R[j][f] * g_tc[t] - g_I[j][f] * g_ts[t];
    }
    ((float*)g_M)[f * DD + k] = m * (1.0f / 16.0f);
    if (e < DD) {
        float cc = 0.f;
        for (int j = 0; j < DD; ++j) {
            int t = (16 * j * e) & 255;
            cc += (br[j] - bi[j]) * g_tc[t] - (br[j] + bi[j]) * g_ts[t];
        }
        g_c[e] = cc * (1.0f / 16.0f);
        g_cnt[e] = 0;
    }
}

// ---------------- K3: main patch GEMM (round-4 proven config) ----------------
// Warp = 64 adjacent patches (8 streams), k split across warp pairs (kh).
// lane l: a = l>>2 (patch sub-index), q = l&3 (s2 quad).
__global__ void __launch_bounds__(128, 4) k_main(const float* __restrict__ x) {
    __shared__ uint4 sM[FEAT * 4];   // row f: unit m stored at col (m+(f>>2))&3
    __shared__ float scc[DD];
    int tid = threadIdx.x;
    {
        const uint4* gm = (const uint4*)g_M;
        for (int f = tid; f < 256; f += 128)
#pragma unroll
            for (int m = 0; m < 4; ++m)
                sM[f * 4 + ((m + (f >> 2)) & 3)] = gm[f * 4 + m];
        if (tid < DD) scc[tid] = g_c[tid];
    }
    __syncthreads();

    uint sMaddr = (uint)__cvta_generic_to_shared(sM);
    int lane = tid & 31;
    int warp = tid >> 5;
    int unit = blockIdx.x * 2 + (warp & 1);   // 2048 units (b, ph, seg)
    int kh = warp >> 1;                       // k half: pairs kh*4 .. kh*4+3
    int b = unit >> 8;
    int r = unit & 255;
    int ph = r >> 1;
    int seg = r & 1;                          // 64-patch column segment
    int a = lane >> 2;
    int q = lane & 3;

    const float* base = x + (size_t)b * HH * WW + (size_t)(ph * PATCH) * WW + seg * 1024;

    ull acc[8][4];
    ull z = packf2(0.f, 0.f);
#pragma unroll
    for (int t = 0; t < 8; ++t)
#pragma unroll
        for (int p = 0; p < 4; ++p) acc[t][p] = z;

    const float4* rp = (const float4*)base;
    float4 cur[8];
#pragma unroll
    for (int t = 0; t < 8; ++t) cur[t] = rp[t * 32 + lane];

    uint c0 = (uint)(((2 * kh + q) & 3) << 4);
    uint c1 = (uint)(((2 * kh + 1 + q) & 3) << 4);

#pragma unroll 1
    for (int s1 = 0; s1 < PATCH; ++s1) {
        uint rowbase = sMaddr + (uint)(s1 * 16 + q * 4) * 64;
#pragma unroll
        for (int e = 0; e < 4; ++e) {
            uint ra = rowbase + (uint)e * 64;
            ull mk0, mk1, mk2, mk3;
            lds_v2u64(mk0, mk1, ra + c0);
            lds_v2u64(mk2, mk3, ra + c1);
#pragma unroll
            for (int t = 0; t < 8; ++t) {
                float xv = (e == 0) ? cur[t].x : (e == 1) ? cur[t].y
                         : (e == 2) ? cur[t].z : cur[t].w;
                ull vp = packf2(xv, xv);
                fmaf2(acc[t][0], vp, mk0);
                fmaf2(acc[t][1], vp, mk1);
                fmaf2(acc[t][2], vp, mk2);
                fmaf2(acc[t][3], vp, mk3);
            }
        }
        if (s1 < 15) {
            const float4* rn = (const float4*)(base + (size_t)(s1 + 1) * WW);
#pragma unroll
            for (int t = 0; t < 8; ++t) cur[t] = rn[t * 32 + lane];
        }
    }

    // reduce-scatter acc[t][0..3] over the 4 quad lanes -> 1 k-pair per lane
    int lp = ((q & 1) << 1) | ((q & 2) >> 1);
    int k0 = (4 * kh + lp) * 2;
    ull cbias = packf2(scc[k0], scc[k0 + 1]);
    float* gp = g_img + (size_t)b * DD * NPIX + ph * 128 + seg * 64;
#pragma unroll
    for (int t = 0; t < 8; ++t) {
        ull tmp0, tmp1, fin;
        {
            ull send = (q & 1) ? acc[t][0] : acc[t][2];
            ull keep = (q & 1) ? acc[t][2] : acc[t][0];
            tmp0 = addf2(keep, __shfl_xor_sync(0xffffffffu, send, 1));
            send = (q & 1) ? acc[t][1] : acc[t][3];
            keep = (q & 1) ? acc[t][3] : acc[t][1];
            tmp1 = addf2(keep, __shfl_xor_sync(0xffffffffu, send, 1));
        }
        {
            ull send = (q & 2) ? tmp0 : tmp1;
            ull keep = (q & 2) ? tmp1 : tmp0;
            fin = addf2(keep, __shfl_xor_sync(0xffffffffu, send, 2));
        }
        ull v = addf2(fin, cbias);
        float lo, hi;
        unpackf2(v, lo, hi);
        int col = t * 8 + a;
        gp[(size_t)k0 * NPIX + col] = lo;
        gp[(size_t)(k0 + 1) * NPIX + col] = hi;
    }
}

// ---------------- float4 + shfl rolling 3x3 conv ----------------
__device__ __forceinline__ void conv_rows(float4 v, int lane, const float* w,
                                          float4& h0, float4& h1, float4& h2) {
    float l = __shfl_up_sync(0xffffffffu, v.w, 1);
    float rr = __shfl_down_sync(0xffffffffu, v.x, 1);
    if (lane == 0) l = 0.f;
    if (lane == 31) rr = 0.f;
    float lx = l, ly = v.x, lz = v.y, lw = v.z;
    float rx = v.y, ry = v.z, rz = v.w, rw = rr;
#define HROW(H, W0, W1, W2)                                   \
    H.x = W0 * lx + W1 * v.x + W2 * rx;                       \
    H.y = W0 * ly + W1 * v.y + W2 * ry;                       \
    H.z = W0 * lz + W1 * v.z + W2 * rz;                       \
    H.w = W0 * lw + W1 * v.w + W2 * rw;
    HROW(h0, w[0], w[1], w[2])
    HROW(h1, w[3], w[4], w[5])
    HROW(h2, w[6], w[7], w[8])
#undef HROW
}

__device__ __forceinline__ float4 ld_row(const float* __restrict__ base, int r, int lane) {
    if ((unsigned)r < 128u) return ((const float4*)(base + r * 128))[lane];
    return make_float4(0.f, 0.f, 0.f, 0.f);
}

// ---------------- K4: fused conv + stats + grid-sync + BN + write -------------
// 1024 blocks x 128 threads: all resident simultaneously. Each block computes
// conv once (values kept in regs), publishes partial sums, release-arrives on
// g_cnt[d]; spins until all 64 partials for channel d exist; re-reduces them
// in fixed order (deterministic), applies BN, stores.
__global__ void __launch_bounds__(128) k_fused(const float* __restrict__ cw,
                                               const float* __restrict__ cb,
                                               const float* __restrict__ gamma,
                                               const float* __restrict__ beta,
                                               float* __restrict__ out) {
    int blk = blockIdx.x;            // bd*8 + slice
    int bd = blk >> 3;
    int d = bd & 15;
    int slice = blk & 7;
    int tid = threadIdx.x;
    int lane = tid & 31, wp = tid >> 5;
    int r0 = slice * 16 + wp * 4;
    float w[9];
#pragma unroll
    for (int t = 0; t < 9; ++t) w[t] = cw[d * 9 + t];
    float bias = cb[d];
    const float* base = g_img + (size_t)bd * NPIX;

    float4 A = make_float4(0, 0, 0, 0), B = make_float4(0, 0, 0, 0);
    float4 cv[4];
    float s = 0.f, sq = 0.f;
#pragma unroll
    for (int r = r0 - 1; r <= r0 + 4; ++r) {
        float4 v = ld_row(base, r, lane);
        float4 h0, h1, h2;
        conv_rows(v, lane, w, h0, h1, h2);
        if (r >= r0 + 1) {
            float4 o;
            o.x = A.x + h2.x + bias;
            o.y = A.y + h2.y + bias;
            o.z = A.z + h2.z + bias;
            o.w = A.w + h2.w + bias;
            cv[r - 1 - r0] = o;
            s += o.x + o.y + o.z + o.w;
            sq += o.x * o.x + o.y * o.y + o.z * o.z + o.w * o.w;
        }
        A.x = B.x + h1.x; A.y = B.y + h1.y; A.z = B.z + h1.z; A.w = B.w + h1.w;
        B = h0;
    }
#pragma unroll
    for (int off = 16; off; off >>= 1) {
        s += __shfl_down_sync(0xffffffffu, s, off);
        sq += __shfl_down_sync(0xffffffffu, sq, off);
    }
    __shared__ float rs[4], rq[4];
    if (lane == 0) { rs[wp] = s; rq[wp] = sq; }
    __syncthreads();
    if (tid == 0) {
        g_ps[blk] = rs[0] + rs[1] + rs[2] + rs[3];
        g_pq[blk] = rq[0] + rq[1] + rq[2] + rq[3];
        __threadfence();                       // release partials
        atomicAdd(&g_cnt[d], 1);
        while (atomicAdd(&g_cnt[d], 0) < 64) {}  // acquire via L2 atomic poll
    }
    __syncthreads();

    // deterministic re-reduce of this channel's 64 partials (L2 loads, fixed order)
    __shared__ float sp[64], sq2[64];
    __shared__ float smu, ssc;
    if (tid < 64) {
        int bb = tid >> 3, sl = tid & 7;
        int idx = ((bb * DD + d) << 3) + sl;
        sp[tid] = __ldcg(&g_ps[idx]);
        sq2[tid] = __ldcg(&g_pq[idx]);
    }
    __syncthreads();
    for (int off = 32; off; off >>= 1) {
        if (tid < off) { sp[tid] += sp[tid + off]; sq2[tid] += sq2[tid + off]; }
        __syncthreads();
    }
    if (tid == 0) {
        float n = 131072.0f;
        float mu = sp[0] / n;
        float var = sq2[0] / n - mu * mu;
        smu = mu;
        ssc = rsqrtf(var + 1e-5f) * gamma[d];
    }
    __syncthreads();
    float mu = smu, sc = ssc, bt = beta[d];

    float4* op = (float4*)(out + (size_t)bd * NPIX) + lane;
#pragma unroll
    for (int ri = 0; ri < 4; ++ri) {
        float4 o;
        o.x = (cv[ri].x - mu) * sc + bt;
        o.y = (cv[ri].y - mu) * sc + bt;
        o.z = (cv[ri].z - mu) * sc + bt;
        o.w = (cv[ri].w - mu) * sc + bt;
        op[(r0 + ri) * 32] = o;
    }
}

extern "C" void kernel_launch(void* const* d_in, const int* in_sizes, int n_in,
                              void* d_out, int out_size) {
    const float* x = (const float*)d_in[0];
    const float* Wr = (const float*)d_in[1];
    const float* br = (const float*)d_in[2];
    const float* Wi = (const float*)d_in[3];
    const float* bi = (const float*)d_in[4];
    const float* cw = (const float*)d_in[5];
    const float* cb = (const float*)d_in[6];
    const float* gamma = (const float*)d_in[7];
    const float* beta = (const float*)d_in[8];
    float* out = (float*)d_out;

    k_prep1<<<16, 256>>>(Wr, Wi);
    k_prep2<<<16, 256>>>(br, bi);
    k_main<<<1024, 128>>>(x);
    k_fused<<<1024, 128>>>(cw, cb, gamma, beta, out);
}